// round 8
// baseline (speedup 1.0000x reference)
#include <cuda_runtime.h>
#include <cuda_fp16.h>
#include <cstdint>

#define B_   8
#define D_   512
#define L_   4096
#define LXP  4160      // padded row length for k-major X (16B-aligned, halo+zeros)
#define T_   8192
#define KS   17

// ---------------- device scratch ----------------
__device__ __half g_A[3][D_][D_];         // folded weights fp16 [k][e][c]
__device__ __half g_Xc[B_][D_][LXP];      // x fp16, k-major [b][c][i], pad zeros
__device__ __half g_Xs[B_][D_][LXP];      // x shifted by +1: g_Xs[b][c][i] = x[i+1]
__device__ float  g_cb[D_];               // projected conv bias
__device__ __half g_z[(size_t)B_ * D_ * T_];   // intermediate (67 MB, fp16)

// ---------------- PTX helpers ----------------
__device__ __forceinline__ uint32_t smem_u32(const void* p) {
    uint32_t a;
    asm("{ .reg .u64 t; cvta.to.shared.u64 t, %1; cvt.u32.u64 %0, t; }" : "=r"(a) : "l"(p));
    return a;
}
__device__ __forceinline__ void cp16(uint32_t dst, const void* src) {
    asm volatile("cp.async.cg.shared.global [%0], [%1], 16;" :: "r"(dst), "l"(src));
}
#define CP_COMMIT()  asm volatile("cp.async.commit_group;" ::: "memory")
#define CP_WAIT2()   asm volatile("cp.async.wait_group 2;" ::: "memory")

__device__ __forceinline__ void ldsm_x4(uint32_t* r, uint32_t addr) {
    asm volatile("ldmatrix.sync.aligned.m8n8.x4.shared.b16 {%0,%1,%2,%3}, [%4];"
                 : "=r"(r[0]), "=r"(r[1]), "=r"(r[2]), "=r"(r[3]) : "r"(addr));
}
__device__ __forceinline__ void ldsm_x4_t(uint32_t* r, uint32_t addr) {
    asm volatile("ldmatrix.sync.aligned.m8n8.x4.trans.shared.b16 {%0,%1,%2,%3}, [%4];"
                 : "=r"(r[0]), "=r"(r[1]), "=r"(r[2]), "=r"(r[3]) : "r"(addr));
}
__device__ __forceinline__ void mma_fp16(float* d, const uint32_t* a, const uint32_t* b) {
    asm volatile("mma.sync.aligned.m16n8k16.row.col.f32.f16.f16.f32 "
                 "{%0,%1,%2,%3}, {%4,%5,%6,%7}, {%8,%9}, {%0,%1,%2,%3};"
                 : "+f"(d[0]), "+f"(d[1]), "+f"(d[2]), "+f"(d[3])
                 : "r"(a[0]), "r"(a[1]), "r"(a[2]), "r"(a[3]), "r"(b[0]), "r"(b[1]));
}
__device__ __forceinline__ unsigned long long pack2(float lo, float hi) {
    unsigned long long r;
    asm("mov.b64 %0, {%1, %2};" : "=l"(r) : "f"(lo), "f"(hi));
    return r;
}
__device__ __forceinline__ unsigned long long fma2(unsigned long long a,
                                                   unsigned long long b,
                                                   unsigned long long c) {
    unsigned long long d;
    asm("fma.rn.f32x2 %0, %1, %2, %3;" : "=l"(d) : "l"(a), "l"(b), "l"(c));
    return d;
}
__device__ __forceinline__ float2 unpack2(unsigned long long v) {
    float2 f;
    asm("mov.b64 {%0, %1}, %2;" : "=f"(f.x), "=f"(f.y) : "l"(v));
    return f;
}

// ---------------- kernel 1 (merged prep): fold | cb | convert ----------------
// blocks [0,256)    : fold (tile 32e x 32c x 3k; thread 2e x 2c x 3k)
// blocks [256,258)  : cb
// blocks [258,4354) : convert one (b,c) row of x -> g_Xc, g_Xs (fp16)
#define FOLD_BLKS 256
#define CB_BLKS   2
#define CONV_BLKS 4096
#define PREP_GRID (FOLD_BLKS + CB_BLKS + CONV_BLKS)

__global__ __launch_bounds__(256, 5) void prep_kernel(const float* __restrict__ x,
                                                      const float* __restrict__ conv_w,
                                                      const float* __restrict__ conv_b,
                                                      const float* __restrict__ proj_w) {
    __shared__ float sm[32 * 33 + 32 * 98];
    const int bx = blockIdx.x;
    const int t  = threadIdx.x;

    if (bx < FOLD_BLKS) {
        // ---- fold ----
        float (*sP)[33] = (float (*)[33])sm;               // [d][e]
        float (*sW)[98] = (float (*)[98])(sm + 32 * 33);   // [d][c*3+k]
        const int c0 = (bx & 15) * 32;
        const int e0 = (bx >> 4) * 32;
        const int tx = t & 15;
        const int ty = t >> 4;

        float acc[3][2][2];
#pragma unroll
        for (int k = 0; k < 3; k++)
#pragma unroll
            for (int e = 0; e < 2; e++) { acc[k][e][0] = 0.f; acc[k][e][1] = 0.f; }

        for (int d0 = 0; d0 < D_; d0 += 32) {
#pragma unroll
            for (int p = 0; p < 4; p++) {
                int idx = p * 256 + t;
                int e = idx >> 5, d = idx & 31;
                sP[d][e] = proj_w[(size_t)(e0 + e) * D_ + d0 + d];
            }
#pragma unroll
            for (int p = 0; p < 12; p++) {
                int idx = p * 256 + t;
                int d = idx / 96, rem = idx % 96;
                sW[d][rem] = conv_w[(size_t)(d0 + d) * (D_ * 3) + (size_t)c0 * 3 + rem];
            }
            __syncthreads();
#pragma unroll
            for (int dd = 0; dd < 32; dd++) {
                float pe0 = sP[dd][ty * 2 + 0];
                float pe1 = sP[dd][ty * 2 + 1];
#pragma unroll
                for (int c = 0; c < 2; c++)
#pragma unroll
                    for (int k = 0; k < 3; k++) {
                        float w = sW[dd][(tx * 2 + c) * 3 + k];
                        acc[k][0][c] += pe0 * w;
                        acc[k][1][c] += pe1 * w;
                    }
            }
            __syncthreads();
        }
#pragma unroll
        for (int k = 0; k < 3; k++)
#pragma unroll
            for (int e = 0; e < 2; e++)
#pragma unroll
                for (int c = 0; c < 2; c++)
                    g_A[k][e0 + ty * 2 + e][c0 + tx * 2 + c] = __float2half_rn(acc[k][e][c]);
    } else if (bx < FOLD_BLKS + CB_BLKS) {
        // ---- cb ----
        int e = (bx - FOLD_BLKS) * 256 + t;
        if (e < D_) {
            float s = 0.f;
            const float* row = proj_w + (size_t)e * D_;
#pragma unroll 8
            for (int d = 0; d < D_; d++) s += row[d] * conv_b[d];
            g_cb[e] = s;
        }
    } else {
        // ---- convert: one (b,c) row, 256 threads x 16 floats ----
        const int row = bx - (FOLD_BLKS + CB_BLKS);
        const int b = row >> 9, c = row & 511;
        const float* xr = x + ((size_t)b * D_ + c) * L_;
        __half* xc = &g_Xc[b][c][0];
        __half* xs = &g_Xs[b][c][0];
        const int o = t * 16;

        float f[16];
#pragma unroll
        for (int q = 0; q < 4; q++)
            *(float4*)&f[q * 4] = *(const float4*)(xr + o + q * 4);

        float nxt = __shfl_down_sync(0xffffffffu, f[0], 1);
        if ((t & 31) == 31)
            nxt = (o + 16 < L_) ? xr[o + 16] : 0.f;

        // g_Xc[o..o+15] = x[o..o+15]
        {
            __half2 h[8];
#pragma unroll
            for (int m = 0; m < 8; m++) h[m] = __floats2half2_rn(f[2 * m], f[2 * m + 1]);
            uint4 u0, u1;
            u0.x = *(uint32_t*)&h[0]; u0.y = *(uint32_t*)&h[1];
            u0.z = *(uint32_t*)&h[2]; u0.w = *(uint32_t*)&h[3];
            u1.x = *(uint32_t*)&h[4]; u1.y = *(uint32_t*)&h[5];
            u1.z = *(uint32_t*)&h[6]; u1.w = *(uint32_t*)&h[7];
            *(uint4*)(xc + o)     = u0;
            *(uint4*)(xc + o + 8) = u1;
        }
        // g_Xs[o..o+15] = x[o+1..o+16]
        {
            float g[16];
#pragma unroll
            for (int j = 0; j < 15; j++) g[j] = f[j + 1];
            g[15] = nxt;
            __half2 h[8];
#pragma unroll
            for (int m = 0; m < 8; m++) h[m] = __floats2half2_rn(g[2 * m], g[2 * m + 1]);
            uint4 u0, u1;
            u0.x = *(uint32_t*)&h[0]; u0.y = *(uint32_t*)&h[1];
            u0.z = *(uint32_t*)&h[2]; u0.w = *(uint32_t*)&h[3];
            u1.x = *(uint32_t*)&h[4]; u1.y = *(uint32_t*)&h[5];
            u1.z = *(uint32_t*)&h[6]; u1.w = *(uint32_t*)&h[7];
            *(uint4*)(xs + o)     = u0;
            *(uint4*)(xs + o + 8) = u1;
        }
        // zero pad [4096, 4160)
        if (t < 8) {
            uint4 z; z.x = z.y = z.z = z.w = 0u;
            *(uint4*)(xc + L_ + t * 8) = z;
            *(uint4*)(xs + L_ + t * 8) = z;
        }
    }
}

// ---------------- kernel 2: fp16 HMMA GEMM, k-major B via ldmatrix.trans ----
#define KC      32
#define NCH     (D_ / KC)            // 16
#define ROWB    80                   // A row: 32 halfs + pad (5x16B, odd)
#define A_PLANE (128 * ROWB)         // 10240
#define A_SIZE  (3 * A_PLANE)        // 30720
#define ROWXB   272                  // X row: 136 halfs (17x16B, odd)
#define X_COPY  (KC * ROWXB)         // 8704
#define XC_OFF  A_SIZE
#define XS_OFF  (A_SIZE + X_COPY)
#define STAGE   (A_SIZE + 2 * X_COPY)  // 48128
#define NSTAGE  3
#define GEMM_SMEM (NSTAGE * STAGE)   // 144384

__device__ __forceinline__ void load_stage(uint32_t sb, int st, int ch,
                                           int e0, int i0, int b, int t) {
    const int c0 = ch * KC;
    const uint32_t base = sb + (uint32_t)st * STAGE;
    // A: 3 planes x 128 rows x 4 chunks = 1536 ops (3/thread @512)
#pragma unroll
    for (int p = 0; p < 3; p++) {
        int row = t >> 2, cb = t & 3;
        const __half* src = &g_A[p][0][0] + (size_t)(e0 + row) * D_ + c0 + cb * 8;
        cp16(base + p * A_PLANE + row * ROWB + cb * 16, src);
    }
    // X: 2 copies x 32 rows x 17 chunks = 1088 ops
    for (int idx = t; idx < 1088; idx += 512) {
        int copy = idx >= 544;
        int rem = idx - copy * 544;
        int row = rem / 17, cb = rem % 17;
        const __half* src = (copy ? &g_Xs[0][0][0] : &g_Xc[0][0][0])
                            + ((size_t)(b * D_ + c0 + row)) * LXP + i0 + cb * 8;
        cp16(base + (copy ? XS_OFF : XC_OFF) + row * ROWXB + cb * 16, src);
    }
}

__global__ void __launch_bounds__(512, 1) gemm_kernel() {
    extern __shared__ char smem[];
    const uint32_t sb = smem_u32(smem);
    const int t = threadIdx.x, wid = t >> 5, lane = t & 31;
    const int i0 = blockIdx.x * 128, e0 = blockIdx.y * 128, b = blockIdx.z;
    const int e_w = (wid & 3) * 32;
    const int i_w = (wid >> 2) * 32;

    float accE[2][4][4], accO[2][4][4];
#pragma unroll
    for (int mt = 0; mt < 2; mt++)
#pragma unroll
        for (int nt = 0; nt < 4; nt++)
#pragma unroll
            for (int j = 0; j < 4; j++) { accE[mt][nt][j] = 0.f; accO[mt][nt][j] = 0.f; }

    load_stage(sb, 0, 0, e0, i0, b, t);
    CP_COMMIT();
    load_stage(sb, 1, 1, e0, i0, b, t);
    CP_COMMIT();

    // ldmatrix.trans per-lane address pattern within X tile:
    // lanes 0-7: k rows 0-7 @ n0; 8-15: k rows 8-15 @ n0; 16-31: same @ n0+8
    const uint32_t bOff = (uint32_t)((lane & 7) + ((lane >> 3) & 1) * 8) * ROWXB
                        + (uint32_t)(i_w + (lane >> 4) * 8) * 2;
    const uint32_t aRow = (uint32_t)(e_w + (lane & 15)) * ROWB + (uint32_t)(lane >> 4) * 16;

    for (int ch = 0; ch < NCH; ++ch) {
        if (ch + 2 < NCH)
            load_stage(sb, (ch + 2) % NSTAGE, ch + 2, e0, i0, b, t);
        CP_COMMIT();
        CP_WAIT2();
        __syncthreads();

        const uint32_t sA  = sb + (uint32_t)(ch % NSTAGE) * STAGE;
        const uint32_t sXc = sA + XC_OFF;
        const uint32_t sXs = sA + XS_OFF;

#pragma unroll
        for (int kh = 0; kh < 2; ++kh) {
            const uint32_t kbA = (uint32_t)kh * 32;          // bytes within A row
            const uint32_t kbX = (uint32_t)kh * 16 * ROWXB;  // 16 c-rows down
            uint32_t bX[4][2], bS[4][2];
            {
                uint32_t r[4];
                ldsm_x4_t(r, sXc + bOff + kbX);
                bX[0][0] = r[0]; bX[0][1] = r[1]; bX[1][0] = r[2]; bX[1][1] = r[3];
                ldsm_x4_t(r, sXc + bOff + kbX + 32);
                bX[2][0] = r[0]; bX[2][1] = r[1]; bX[3][0] = r[2]; bX[3][1] = r[3];
                ldsm_x4_t(r, sXs + bOff + kbX);
                bS[0][0] = r[0]; bS[0][1] = r[1]; bS[1][0] = r[2]; bS[1][1] = r[3];
                ldsm_x4_t(r, sXs + bOff + kbX + 32);
                bS[2][0] = r[0]; bS[2][1] = r[1]; bS[3][0] = r[2]; bS[3][1] = r[3];
            }
#pragma unroll
            for (int s = 0; s < 3; ++s) {
                uint32_t aF[2][4];
#pragma unroll
                for (int mt = 0; mt < 2; mt++)
                    ldsm_x4(aF[mt], sA + s * A_PLANE + aRow + mt * (16 * ROWB) + kbA);
#pragma unroll
                for (int mt = 0; mt < 2; mt++)
#pragma unroll
                    for (int nt = 0; nt < 4; nt++) {
                        float* d = (s == 1) ? accE[mt][nt] : accO[mt][nt];
                        mma_fp16(d, aF[mt], (s == 2) ? bS[nt] : bX[nt]);
                    }
            }
        }
        __syncthreads();
    }

    // ---- epilogue: interleave even/odd, add folded conv bias, write fp16 z ----
#pragma unroll
    for (int mt = 0; mt < 2; mt++) {
        int r0 = e0 + e_w + mt * 16 + (lane >> 2);
        float cb0 = g_cb[r0], cb1 = g_cb[r0 + 8];
#pragma unroll
        for (int nt = 0; nt < 4; nt++) {
            int ie = i0 + i_w + nt * 8 + (lane & 3) * 2;
            __half2 p0 = __floats2half2_rn(accE[mt][nt][0] + cb0, accO[mt][nt][0] + cb0);
            __half2 p1 = __floats2half2_rn(accE[mt][nt][1] + cb0, accO[mt][nt][1] + cb0);
            __half2 p2 = __floats2half2_rn(accE[mt][nt][2] + cb1, accO[mt][nt][2] + cb1);
            __half2 p3 = __floats2half2_rn(accE[mt][nt][3] + cb1, accO[mt][nt][3] + cb1);
            uint2 u0, u1;
            u0.x = *(uint32_t*)&p0; u0.y = *(uint32_t*)&p1;
            u1.x = *(uint32_t*)&p2; u1.y = *(uint32_t*)&p3;
            *(uint2*)(g_z + ((size_t)(b * D_ + r0)) * T_ + 2 * ie)     = u0;
            *(uint2*)(g_z + ((size_t)(b * D_ + r0 + 8)) * T_ + 2 * ie) = u1;
        }
    }
}

// ---------------- kernel 3: depthwise 17-tap AA, direct-gmem, f32x2 ---------
__device__ __forceinline__ void unp8(uint4 v, float* w) {
    const __half2* h = (const __half2*)&v;
    float2 f0 = __half22float2(h[0]);
    float2 f1 = __half22float2(h[1]);
    float2 f2 = __half22float2(h[2]);
    float2 f3 = __half22float2(h[3]);
    w[0] = f0.x; w[1] = f0.y; w[2] = f1.x; w[3] = f1.y;
    w[4] = f2.x; w[5] = f2.y; w[6] = f3.x; w[7] = f3.y;
}

__global__ __launch_bounds__(256) void aa_kernel(const float* __restrict__ aa,
                                                 const float* __restrict__ pb,
                                                 float* __restrict__ out) {
    const int row = blockIdx.x >> 2;           // b*512 + e
    const int seg = blockIdx.x & 3;
    const int t   = threadIdx.x;
    const int o0  = seg * 2048 + t * 8;
    const __half* zr = g_z + (size_t)row * T_;

    float w[24];
    if (o0 >= 8 && o0 + 16 <= T_) {
        uint4 v0 = *(const uint4*)(zr + o0 - 8);
        uint4 v1 = *(const uint4*)(zr + o0);
        uint4 v2 = *(const uint4*)(zr + o0 + 8);
        unp8(v0, w); unp8(v1, w + 8); unp8(v2, w + 16);
    } else {
#pragma unroll
        for (int j = 0; j < 24; j++) {
            int g = o0 - 8 + j;
            w[j] = (g >= 0 && g < T_) ? __half2float(zr[g]) : 0.f;
        }
    }

    float kc[KS];
#pragma unroll
    for (int j = 0; j < KS; j++) kc[j] = __ldg(&aa[j]);
    float bias = __ldg(&pb[row & (D_ - 1)]);

    unsigned long long E[12], O[11], acc[4];
#pragma unroll
    for (int m = 0; m < 12; m++) E[m] = pack2(w[2 * m], w[2 * m + 1]);
#pragma unroll
    for (int m = 0; m < 11; m++) O[m] = pack2(w[2 * m + 1], w[2 * m + 2]);
    unsigned long long b2 = pack2(bias, bias);
#pragma unroll
    for (int p = 0; p < 4; p++) acc[p] = b2;

#pragma unroll
    for (int j = 0; j < KS; j++) {
        unsigned long long k2 = pack2(kc[j], kc[j]);
        const unsigned long long* src = (j & 1) ? &O[j >> 1] : &E[j >> 1];
#pragma unroll
        for (int p = 0; p < 4; p++) acc[p] = fma2(k2, src[p], acc[p]);
    }

    float* op = out + (size_t)row * T_ + o0;
    float2 a0 = unpack2(acc[0]), a1 = unpack2(acc[1]);
    float2 a2 = unpack2(acc[2]), a3 = unpack2(acc[3]);
    float4 v0, v1;
    v0.x = a0.x; v0.y = a0.y; v0.z = a1.x; v0.w = a1.y;
    v1.x = a2.x; v1.y = a2.y; v1.z = a3.x; v1.w = a3.y;
    *(float4*)op       = v0;
    *(float4*)(op + 4) = v1;
}

// ---------------- launch ----------------
extern "C" void kernel_launch(void* const* d_in, const int* in_sizes, int n_in,
                              void* d_out, int out_size) {
    const float* x      = (const float*)d_in[0];
    const float* conv_w = (const float*)d_in[1];
    const float* conv_b = (const float*)d_in[2];
    const float* aa_k   = (const float*)d_in[3];
    const float* proj_w = (const float*)d_in[4];
    const float* proj_b = (const float*)d_in[5];
    float* out = (float*)d_out;

    cudaFuncSetAttribute(gemm_kernel, cudaFuncAttributeMaxDynamicSharedMemorySize, GEMM_SMEM);

    prep_kernel<<<dim3(PREP_GRID), 256>>>(x, conv_w, conv_b, proj_w);
    gemm_kernel<<<dim3(L_ / 128, D_ / 128, B_), 512, GEMM_SMEM>>>();
    aa_kernel<<<dim3(B_ * D_ * 4), 256>>>(aa_k, proj_b, out);
}

// round 9
// speedup vs baseline: 1.0940x; 1.0940x over previous
#include <cuda_runtime.h>
#include <cuda_fp16.h>
#include <cstdint>

#define B_   8
#define D_   512
#define L_   4096
#define LP_  4097
#define T_   8192
#define KS   17

// ---------------- device scratch ----------------
__device__ __half g_A[3][D_][D_];      // folded weights fp16 [k][e][c]
__device__ __half g_X[B_][LP_][D_];    // transposed x fp16 [b][i][c], row L zeroed
__device__ float  g_cb[D_];            // projected conv bias
__device__ __half g_z[(size_t)B_ * D_ * T_];   // intermediate (67 MB, fp16)

// ---------------- PTX helpers ----------------
__device__ __forceinline__ uint32_t smem_u32(const void* p) {
    uint32_t a;
    asm("{ .reg .u64 t; cvta.to.shared.u64 t, %1; cvt.u32.u64 %0, t; }" : "=r"(a) : "l"(p));
    return a;
}
__device__ __forceinline__ void cp16(uint32_t dst, const void* src) {
    asm volatile("cp.async.cg.shared.global [%0], [%1], 16;" :: "r"(dst), "l"(src));
}
#define CP_COMMIT()  asm volatile("cp.async.commit_group;" ::: "memory")
#define CP_WAIT0()   asm volatile("cp.async.wait_group 0;" ::: "memory")
#define CP_WAIT1()   asm volatile("cp.async.wait_group 1;" ::: "memory")
#define CP_WAIT2()   asm volatile("cp.async.wait_group 2;" ::: "memory")

__device__ __forceinline__ void ldsm_x4(uint32_t* r, uint32_t addr) {
    asm volatile("ldmatrix.sync.aligned.m8n8.x4.shared.b16 {%0,%1,%2,%3}, [%4];"
                 : "=r"(r[0]), "=r"(r[1]), "=r"(r[2]), "=r"(r[3]) : "r"(addr));
}
__device__ __forceinline__ void mma_fp16(float* d, const uint32_t* a, const uint32_t* b) {
    asm volatile("mma.sync.aligned.m16n8k16.row.col.f32.f16.f16.f32 "
                 "{%0,%1,%2,%3}, {%4,%5,%6,%7}, {%8,%9}, {%0,%1,%2,%3};"
                 : "+f"(d[0]), "+f"(d[1]), "+f"(d[2]), "+f"(d[3])
                 : "r"(a[0]), "r"(a[1]), "r"(a[2]), "r"(a[3]), "r"(b[0]), "r"(b[1]));
}
__device__ __forceinline__ unsigned long long pack2(float lo, float hi) {
    unsigned long long r;
    asm("mov.b64 %0, {%1, %2};" : "=l"(r) : "f"(lo), "f"(hi));
    return r;
}
__device__ __forceinline__ unsigned long long fma2(unsigned long long a,
                                                   unsigned long long b,
                                                   unsigned long long c) {
    unsigned long long d;
    asm("fma.rn.f32x2 %0, %1, %2, %3;" : "=l"(d) : "l"(a), "l"(b), "l"(c));
    return d;
}
__device__ __forceinline__ float2 unpack2(unsigned long long v) {
    float2 f;
    asm("mov.b64 {%0, %1}, %2;" : "=f"(f.x), "=f"(f.y) : "l"(v));
    return f;
}

// ---------------- kernel 1 (merged prep): fold | cb | convert-transpose -----
// blocks [0,256)     : fold (tile 32e x 32c x 3k; thread 2e x 2c x 3k)
// blocks [256,258)   : cb + zero row L of g_X
// blocks [258,1282)  : convert-transpose, 256i x 64c slab, cp.async pipelined
#define FOLD_BLKS 256
#define CB_BLKS   2
#define CONV_BLKS 1024
#define PREP_GRID (FOLD_BLKS + CB_BLKS + CONV_BLKS)
#define XS 72                       // smem row stride (words); 288B, 16B-aligned

__global__ __launch_bounds__(256, 4) void prep_kernel(const float* __restrict__ x,
                                                      const float* __restrict__ conv_w,
                                                      const float* __restrict__ conv_b,
                                                      const float* __restrict__ proj_w) {
    __shared__ float sm[2 * 64 * XS];   // 36864 B; fold uses a prefix
    const int bx = blockIdx.x;
    const int t  = threadIdx.x;

    if (bx < FOLD_BLKS) {
        // ---- fold ----
        float (*sP)[33] = (float (*)[33])sm;               // [d][e]
        float (*sW)[98] = (float (*)[98])(sm + 32 * 33);   // [d][c*3+k]
        const int c0 = (bx & 15) * 32;
        const int e0 = (bx >> 4) * 32;
        const int tx = t & 15;
        const int ty = t >> 4;

        float acc[3][2][2];
#pragma unroll
        for (int k = 0; k < 3; k++)
#pragma unroll
            for (int e = 0; e < 2; e++) { acc[k][e][0] = 0.f; acc[k][e][1] = 0.f; }

        for (int d0 = 0; d0 < D_; d0 += 32) {
#pragma unroll
            for (int p = 0; p < 4; p++) {
                int idx = p * 256 + t;
                int e = idx >> 5, d = idx & 31;
                sP[d][e] = proj_w[(size_t)(e0 + e) * D_ + d0 + d];
            }
#pragma unroll
            for (int p = 0; p < 12; p++) {
                int idx = p * 256 + t;
                int d = idx / 96, rem = idx % 96;
                sW[d][rem] = conv_w[(size_t)(d0 + d) * (D_ * 3) + (size_t)c0 * 3 + rem];
            }
            __syncthreads();
#pragma unroll
            for (int dd = 0; dd < 32; dd++) {
                float pe0 = sP[dd][ty * 2 + 0];
                float pe1 = sP[dd][ty * 2 + 1];
#pragma unroll
                for (int c = 0; c < 2; c++)
#pragma unroll
                    for (int k = 0; k < 3; k++) {
                        float w = sW[dd][(tx * 2 + c) * 3 + k];
                        acc[k][0][c] += pe0 * w;
                        acc[k][1][c] += pe1 * w;
                    }
            }
            __syncthreads();
        }
#pragma unroll
        for (int k = 0; k < 3; k++)
#pragma unroll
            for (int e = 0; e < 2; e++)
#pragma unroll
                for (int c = 0; c < 2; c++)
                    g_A[k][e0 + ty * 2 + e][c0 + tx * 2 + c] = __float2half_rn(acc[k][e][c]);
    } else if (bx < FOLD_BLKS + CB_BLKS) {
        // ---- cb + zero halo row of g_X ----
        int u = (bx - FOLD_BLKS) * 256 + t;   // 0..511
        {
            float s = 0.f;
            const float* row = proj_w + (size_t)u * D_;
#pragma unroll 8
            for (int d = 0; d < D_; d++) s += row[d] * conv_b[d];
            g_cb[u] = s;
        }
        {
            int b = u >> 6, c = (u & 63) * 8;
            uint4 z; z.x = z.y = z.z = z.w = 0u;
            *(uint4*)(&g_X[0][0][0] + ((size_t)b * LP_ + L_) * D_ + c) = z;
        }
    } else {
        // ---- convert-transpose: 4 sub-tiles of 64i x 64c, double-buffered ----
        const int bx2 = bx - (FOLD_BLKS + CB_BLKS);
        const int b  = bx2 >> 7;              // 8
        const int cg = (bx2 >> 4) & 7;        // 8
        const int ig = bx2 & 15;              // 16
        const int c0 = cg * 64;
        const int ibase = ig * 256;
        const uint32_t sb = smem_u32(sm);
        const float* xb = x + ((size_t)b * D_ + c0) * L_;
        __half* Xb = &g_X[0][0][0] + (size_t)b * LP_ * D_;

        // thread roles
        const int lc  = t >> 4;               // load: c row (0..15 step, 4 passes)
        const int lch = t & 15;               // load: 16B chunk within 256B row
        const int ri  = t & 63;               // read: i within tile (low bits!)
        const int rc8 = (t >> 6) * 8;         // read: c8 base (p adds 32)

        // prologue: load sub-tile 0 into buf 0
#pragma unroll
        for (int q = 0; q < 4; q++) {
            int c = q * 16 + lc;
            cp16(sb + (uint32_t)(c * XS + lch * 4) * 4,
                 xb + (size_t)c * L_ + ibase + lch * 4);
        }
        CP_COMMIT();

#pragma unroll
        for (int it = 0; it < 4; ++it) {
            const int i0 = ibase + it * 64;
            if (it + 1 < 4) {
                const uint32_t dstb = sb + (uint32_t)(((it + 1) & 1) * 64 * XS) * 4;
#pragma unroll
                for (int q = 0; q < 4; q++) {
                    int c = q * 16 + lc;
                    cp16(dstb + (uint32_t)(c * XS + lch * 4) * 4,
                         xb + (size_t)c * L_ + i0 + 64 + lch * 4);
                }
                CP_COMMIT();
                CP_WAIT1();
            } else {
                CP_WAIT0();
            }
            __syncthreads();

            const float* buf = sm + (it & 1) * 64 * XS;
#pragma unroll
            for (int p = 0; p < 2; p++) {
                int c8 = rc8 + p * 32;
                float f[8];
#pragma unroll
                for (int j = 0; j < 8; j++) f[j] = buf[(c8 + j) * XS + ri];
                __half2 h0 = __floats2half2_rn(f[0], f[1]);
                __half2 h1 = __floats2half2_rn(f[2], f[3]);
                __half2 h2 = __floats2half2_rn(f[4], f[5]);
                __half2 h3 = __floats2half2_rn(f[6], f[7]);
                uint4 u;
                u.x = *(uint32_t*)&h0; u.y = *(uint32_t*)&h1;
                u.z = *(uint32_t*)&h2; u.w = *(uint32_t*)&h3;
                *(uint4*)(Xb + (size_t)(i0 + ri) * D_ + c0 + c8) = u;
            }
            __syncthreads();
        }
    }
}

// ---------------- kernel 2: single-pass fp16 HMMA GEMM (round-7 version) ----
#define KC      64
#define NCH     (D_ / KC)            // 8
#define ROWB    144
#define A_PLANE (128 * ROWB)         // 18432
#define A_SIZE  (3 * A_PLANE)        // 55296
#define X_ROWS  129
#define X_SIZE  (X_ROWS * ROWB)      // 18576
#define STAGE   (A_SIZE + X_SIZE)    // 73872
#define NSTAGE  3
#define GEMM_SMEM (NSTAGE * STAGE)   // 221616

__device__ __forceinline__ void load_stage(uint32_t sb, int st, int ch,
                                           int e0, int i0, int b, int t) {
    const int c0 = ch * KC;
    const uint32_t base = sb + (uint32_t)st * STAGE;
#pragma unroll
    for (int p = 0; p < 6; p++) {
        int idx = p * 512 + t;
        int plane = idx >> 10;
        int rem = idx & 1023;
        int row = rem >> 3, cb = rem & 7;
        const __half* src = &g_A[plane][0][0] + (size_t)(e0 + row) * D_ + c0 + cb * 8;
        cp16(base + plane * A_PLANE + row * ROWB + cb * 16, src);
    }
    for (int idx = t; idx < X_ROWS * 8; idx += 512) {
        int row = idx >> 3, cb = idx & 7;
        const __half* src = &g_X[b][0][0] + (size_t)(i0 + row) * D_ + c0 + cb * 8;
        cp16(base + A_SIZE + row * ROWB + cb * 16, src);
    }
}

__global__ void __launch_bounds__(512, 1) gemm_kernel() {
    extern __shared__ char smem[];
    const uint32_t sb = smem_u32(smem);
    const int t = threadIdx.x, wid = t >> 5, lane = t & 31;
    const int i0 = blockIdx.x * 128, e0 = blockIdx.y * 128, b = blockIdx.z;
    const int e_w = (wid & 3) * 32;
    const int i_w = (wid >> 2) * 32;

    float accE[2][4][4], accO[2][4][4];
#pragma unroll
    for (int mt = 0; mt < 2; mt++)
#pragma unroll
        for (int nt = 0; nt < 4; nt++)
#pragma unroll
            for (int j = 0; j < 4; j++) { accE[mt][nt][j] = 0.f; accO[mt][nt][j] = 0.f; }

    load_stage(sb, 0, 0, e0, i0, b, t);
    CP_COMMIT();
    load_stage(sb, 1, 1, e0, i0, b, t);
    CP_COMMIT();

    for (int ch = 0; ch < NCH; ++ch) {
        if (ch + 2 < NCH)
            load_stage(sb, (ch + 2) % NSTAGE, ch + 2, e0, i0, b, t);
        CP_COMMIT();
        CP_WAIT2();
        __syncthreads();

        const uint32_t sA = sb + (uint32_t)(ch % NSTAGE) * STAGE;
        const uint32_t sX = sA + A_SIZE;
        const uint32_t aRow = (uint32_t)(e_w + (lane & 15)) * ROWB + (uint32_t)(lane >> 4) * 16;
        const uint32_t xRow = sX + (uint32_t)(i_w + lane) * ROWB;

#pragma unroll
        for (int kh = 0; kh < 4; ++kh) {
            const uint32_t kb = (uint32_t)kh * 32;
            uint32_t bX[4][2], bS[4][2];
            {
                uint32_t r1[4], r2[4];
                ldsm_x4(r1, xRow + kb);
                ldsm_x4(r2, xRow + kb + 16);
#pragma unroll
                for (int nt = 0; nt < 4; nt++) { bX[nt][0] = r1[nt]; bX[nt][1] = r2[nt]; }
                ldsm_x4(r1, xRow + ROWB + kb);
                ldsm_x4(r2, xRow + ROWB + kb + 16);
#pragma unroll
                for (int nt = 0; nt < 4; nt++) { bS[nt][0] = r1[nt]; bS[nt][1] = r2[nt]; }
            }
#pragma unroll
            for (int s = 0; s < 3; ++s) {
                uint32_t aF[2][4];
#pragma unroll
                for (int mt = 0; mt < 2; mt++)
                    ldsm_x4(aF[mt], sA + s * A_PLANE + aRow + mt * (16 * ROWB) + kb);
#pragma unroll
                for (int mt = 0; mt < 2; mt++)
#pragma unroll
                    for (int nt = 0; nt < 4; nt++) {
                        float* d = (s == 1) ? accE[mt][nt] : accO[mt][nt];
                        mma_fp16(d, aF[mt], (s == 2) ? bS[nt] : bX[nt]);
                    }
            }
        }
        __syncthreads();
    }

    // ---- epilogue: interleave even/odd, add folded conv bias, write fp16 z ----
#pragma unroll
    for (int mt = 0; mt < 2; mt++) {
        int r0 = e0 + e_w + mt * 16 + (lane >> 2);
        float cb0 = g_cb[r0], cb1 = g_cb[r0 + 8];
#pragma unroll
        for (int nt = 0; nt < 4; nt++) {
            int ie = i0 + i_w + nt * 8 + (lane & 3) * 2;
            __half2 p0 = __floats2half2_rn(accE[mt][nt][0] + cb0, accO[mt][nt][0] + cb0);
            __half2 p1 = __floats2half2_rn(accE[mt][nt][1] + cb0, accO[mt][nt][1] + cb0);
            __half2 p2 = __floats2half2_rn(accE[mt][nt][2] + cb1, accO[mt][nt][2] + cb1);
            __half2 p3 = __floats2half2_rn(accE[mt][nt][3] + cb1, accO[mt][nt][3] + cb1);
            uint2 u0, u1;
            u0.x = *(uint32_t*)&p0; u0.y = *(uint32_t*)&p1;
            u1.x = *(uint32_t*)&p2; u1.y = *(uint32_t*)&p3;
            *(uint2*)(g_z + ((size_t)(b * D_ + r0)) * T_ + 2 * ie)     = u0;
            *(uint2*)(g_z + ((size_t)(b * D_ + r0 + 8)) * T_ + 2 * ie) = u1;
        }
    }
}

// ---------------- kernel 3: depthwise 17-tap AA, direct-gmem, f32x2 ---------
__device__ __forceinline__ void unp8(uint4 v, float* w) {
    const __half2* h = (const __half2*)&v;
    float2 f0 = __half22float2(h[0]);
    float2 f1 = __half22float2(h[1]);
    float2 f2 = __half22float2(h[2]);
    float2 f3 = __half22float2(h[3]);
    w[0] = f0.x; w[1] = f0.y; w[2] = f1.x; w[3] = f1.y;
    w[4] = f2.x; w[5] = f2.y; w[6] = f3.x; w[7] = f3.y;
}

__global__ __launch_bounds__(256) void aa_kernel(const float* __restrict__ aa,
                                                 const float* __restrict__ pb,
                                                 float* __restrict__ out) {
    const int row = blockIdx.x >> 2;           // b*512 + e
    const int seg = blockIdx.x & 3;
    const int t   = threadIdx.x;
    const int o0  = seg * 2048 + t * 8;
    const __half* zr = g_z + (size_t)row * T_;

    float w[24];
    if (o0 >= 8 && o0 + 16 <= T_) {
        uint4 v0 = *(const uint4*)(zr + o0 - 8);
        uint4 v1 = *(const uint4*)(zr + o0);
        uint4 v2 = *(const uint4*)(zr + o0 + 8);
        unp8(v0, w); unp8(v1, w + 8); unp8(v2, w + 16);
    } else {
#pragma unroll
        for (int j = 0; j < 24; j++) {
            int g = o0 - 8 + j;
            w[j] = (g >= 0 && g < T_) ? __half2float(zr[g]) : 0.f;
        }
    }

    float kc[KS];
#pragma unroll
    for (int j = 0; j < KS; j++) kc[j] = __ldg(&aa[j]);
    float bias = __ldg(&pb[row & (D_ - 1)]);

    unsigned long long E[12], O[11], acc[4];
#pragma unroll
    for (int m = 0; m < 12; m++) E[m] = pack2(w[2 * m], w[2 * m + 1]);
#pragma unroll
    for (int m = 0; m < 11; m++) O[m] = pack2(w[2 * m + 1], w[2 * m + 2]);
    unsigned long long b2 = pack2(bias, bias);
#pragma unroll
    for (int p = 0; p < 4; p++) acc[p] = b2;

#pragma unroll
    for (int j = 0; j < KS; j++) {
        unsigned long long k2 = pack2(kc[j], kc[j]);
        const unsigned long long* src = (j & 1) ? &O[j >> 1] : &E[j >> 1];
#pragma unroll
        for (int p = 0; p < 4; p++) acc[p] = fma2(k2, src[p], acc[p]);
    }

    float* op = out + (size_t)row * T_ + o0;
    float2 a0 = unpack2(acc[0]), a1 = unpack2(acc[1]);
    float2 a2 = unpack2(acc[2]), a3 = unpack2(acc[3]);
    float4 v0, v1;
    v0.x = a0.x; v0.y = a0.y; v0.z = a1.x; v0.w = a1.y;
    v1.x = a2.x; v1.y = a2.y; v1.z = a3.x; v1.w = a3.y;
    *(float4*)op       = v0;
    *(float4*)(op + 4) = v1;
}

// ---------------- launch ----------------
extern "C" void kernel_launch(void* const* d_in, const int* in_sizes, int n_in,
                              void* d_out, int out_size) {
    const float* x      = (const float*)d_in[0];
    const float* conv_w = (const float*)d_in[1];
    const float* conv_b = (const float*)d_in[2];
    const float* aa_k   = (const float*)d_in[3];
    const float* proj_w = (const float*)d_in[4];
    const float* proj_b = (const float*)d_in[5];
    float* out = (float*)d_out;

    cudaFuncSetAttribute(gemm_kernel, cudaFuncAttributeMaxDynamicSharedMemorySize, GEMM_SMEM);

    prep_kernel<<<dim3(PREP_GRID), 256>>>(x, conv_w, conv_b, proj_w);
    gemm_kernel<<<dim3(L_ / 128, D_ / 128, B_), 512, GEMM_SMEM>>>();
    aa_kernel<<<dim3(B_ * D_ * 4), 256>>>(aa_k, proj_b, out);
}